// round 7
// baseline (speedup 1.0000x reference)
#include <cuda_runtime.h>

// ---------------------------------------------------------------------------
// 5-layer stacked LSTM, H=51, B=256, T=2048. Output depends only on layer-3 h
// => layers 4,5 dead. 3 roles (L1,L2,L3) x 32 batch groups = 96 CTAs.
// 4-way k-split GEMV: quadrants {input,recurrent} x {k<25,k>=25}, each 7 warps
// (224 padded rows), 28 compute warps + 1 comm warp = 928 threads. Partial
// gates in 4 SMEM buffers summed in the cell update. f32x2 packed FMA,
// register-resident weights (26/thread), deep prefetch D=4 via comm warp.
// ---------------------------------------------------------------------------

#define HN 51
#define NJ 204
#define TN 2048
#define NG 32
#define BT 8
#define NSLOT 16             // ring slots (power of 2)
#define XBUF 8               // xin SMEM slots (power of 2), > DPRE
#define DPRE 4               // prefetch distance
#define QR 224               // padded rows per quadrant (7 warps)
#define NTH 928
#define COMM0 896            // first tid of comm warp (warp 28)
#define KITER 26             // k iterations per half

typedef unsigned long long ull;

__device__ float    g_hbuf[2][NG][NSLOT][HN * BT];
__device__ unsigned g_prod[2][NG];
__device__ unsigned g_cons[2][NG];

__device__ __forceinline__ unsigned ld_acq(const unsigned* p) {
    unsigned v;
    asm volatile("ld.global.acquire.gpu.u32 %0, [%1];" : "=r"(v) : "l"(p));
    return v;
}
__device__ __forceinline__ void st_rel(unsigned* p, unsigned v) {
    asm volatile("st.global.release.gpu.u32 [%0], %1;" :: "l"(p), "r"(v));
}
__device__ __forceinline__ void wait_ge(unsigned* p, unsigned v) {
    if (ld_acq(p) >= v) return;
    while (ld_acq(p) < v) __nanosleep(32);
}
__device__ __forceinline__ float4 ldcg4(const float4* p) {
    float4 v;
    asm volatile("ld.global.cg.v4.f32 {%0,%1,%2,%3}, [%4];"
                 : "=f"(v.x), "=f"(v.y), "=f"(v.z), "=f"(v.w) : "l"(p));
    return v;
}
__device__ __forceinline__ ull ffma2(ull a, ull b, ull c) {
    ull d;
    asm("fma.rn.f32x2 %0, %1, %2, %3;" : "=l"(d) : "l"(a), "l"(b), "l"(c));
    return d;
}
__device__ __forceinline__ ull splat2(float x) {
    ull d; unsigned u = __float_as_uint(x);
    asm("mov.b64 %0, {%1, %2};" : "=l"(d) : "r"(u), "r"(u));
    return d;
}
__device__ __forceinline__ float sigf(float x) {
    return __fdividef(1.f, 1.f + __expf(-x));
}
__device__ __forceinline__ float tanhfast(float x) {
    return 2.f * __fdividef(1.f, 1.f + __expf(-2.f * x)) - 1.f;
}

__global__ void __launch_bounds__(64, 1) reset_kernel() {
    int i = threadIdx.x;
    if (i < NG) {
        g_prod[0][i] = 0; g_prod[1][i] = 0;
        g_cons[0][i] = 0; g_cons[1][i] = 0;
    }
}

__global__ void __launch_bounds__(NTH, 1) lstm_kernel(
    const float* __restrict__ x,    const float* __restrict__ Wih1,
    const float* __restrict__ Whh1, const float* __restrict__ bih1,
    const float* __restrict__ bhh1, const float* __restrict__ Wih,
    const float* __restrict__ Whh,  const float* __restrict__ bih,
    const float* __restrict__ bhh,  const float* __restrict__ Wl,
    const float* __restrict__ bl,   float* __restrict__ out)
{
    __shared__ __align__(16) float xin[XBUF][HN * BT];  // layer-input slots
    __shared__ __align__(16) float h_t[HN * BT];        // [k][b]
    __shared__ __align__(16) float c_s[HN * BT];
    __shared__ __align__(16) float gbuf[4][NJ * BT];    // partial gates per quadrant
    __shared__ __align__(16) float xchunk[32 * BT];     // [q][b], L1 raw-x prefetch
    __shared__ float wl_s[52];

    const int tid  = threadIdx.x;
    const int role = blockIdx.x / NG;   // 0=L1, 1=L2, 2=L3
    const int g    = blockIdx.x % NG;

    const bool is_comm = (tid >= COMM0);
    const int  quad    = is_comm ? 0 : (tid / QR);      // 0,1: input; 2,3: recurrent
    const int  jraw    = is_comm ? 0 : (tid % QR);
    const bool is_in   = (quad < 2);
    const int  kh      = quad & 1;                      // k half
    const int  kbase   = kh * (KITER - 1);              // 0 or 25
    const bool active  = (!is_comm) && (jraw < NJ) && !(role == 0 && quad == 1);
    const int  j       = (jraw < NJ) ? jraw : 0;

    // ---------------- per-thread register weights ----------------
    float w_r[KITER];
    ull bias2 = 0, w1_2 = 0;
    if (active) {
        if (role == 0) {
            if (quad == 0) {
                bias2 = splat2(bih1[j] + bhh1[j]);
                w1_2  = splat2(Wih1[j]);
            } else {  // quad 2,3: recurrent halves
                #pragma unroll
                for (int k = 0; k < KITER; k++)
                    w_r[k] = (k == 0 && kh) ? 0.f : Whh1[j * HN + kbase + k];
            }
        } else {
            const int l = role - 1;
            const float* Wp = is_in ? (Wih + (l * NJ + j) * HN)
                                    : (Whh + (l * NJ + j) * HN);
            #pragma unroll
            for (int k = 0; k < KITER; k++)
                w_r[k] = (k == 0 && kh) ? 0.f : Wp[kbase + k];
            if (is_in && kh == 0)
                bias2 = splat2(bih[l * NJ + j] + bhh[l * NJ + j]);
        }
    }
    if (role == 2 && tid < HN) wl_s[tid] = Wl[tid];
    const float blv = (role == 2) ? bl[0] : 0.f;
    for (int i = tid; i < HN * BT; i += NTH) { h_t[i] = 0.f; c_s[i] = 0.f; }
    for (int i = tid; i < 4 * NJ * BT; i += NTH) (&gbuf[0][0])[i] = 0.f;
    __syncthreads();

    float*       ring_out = (role < 2) ? &g_hbuf[role][g][0][0]     : (float*)0;
    const float* ring_in  = (role > 0) ? &g_hbuf[role - 1][g][0][0] : (const float*)0;

    // ---- prologue: comm warp prefetches slots 0..DPRE-1 (persistent lead) ----
    if (role > 0 && is_comm) {
        for (int d = 0; d < DPRE; d++) {
            if (tid == COMM0) wait_ge(&g_prod[role - 1][g], (unsigned)(d + 1));
            __syncwarp();
            const float4* src = (const float4*)(ring_in + (d & (NSLOT - 1)) * HN * BT);
            float4* dst = (float4*)xin[d & (XBUF - 1)];
            for (int i = tid - COMM0; i < HN * BT / 4; i += 32) dst[i] = ldcg4(src + i);
            __syncwarp();
            if (tid == COMM0) st_rel(&g_cons[role - 1][g], (unsigned)(d + 1));
        }
    }
    __syncthreads();

    for (int t = 0; t < TN; t++) {
        // ---- L1: refill 32-step x chunk (coalesced), transposed [q][b] ----
        if (role == 0 && (t & 31) == 0) {
            if (tid < 256) {
                int b = tid >> 5, q = tid & 31;
                xchunk[q * BT + b] = x[(size_t)(g * BT + b) * TN + t + q];
            }
            __syncthreads();
        }

        // ================= P0: quarter-GEMVs + comm =================
        if (!is_comm) {
            ull a0 = bias2, a1 = bias2, a2 = bias2, a3 = bias2;
            if (role == 0) {
                if (quad == 0) {
                    const ulonglong2* xp = (const ulonglong2*)&xchunk[(t & 31) * BT];
                    ulonglong2 X0 = xp[0], X1 = xp[1];
                    a0 = ffma2(X0.x, w1_2, a0); a1 = ffma2(X0.y, w1_2, a1);
                    a2 = ffma2(X1.x, w1_2, a2); a3 = ffma2(X1.y, w1_2, a3);
                } else if (quad >= 2) {
                    const ulonglong2* hp = (const ulonglong2*)&h_t[kbase * BT];
                    #pragma unroll
                    for (int k = 0; k < KITER; k++) {
                        ulonglong2 H0 = hp[2 * k], H1 = hp[2 * k + 1];
                        ull w2 = splat2(w_r[k]);
                        a0 = ffma2(H0.x, w2, a0); a1 = ffma2(H0.y, w2, a1);
                        a2 = ffma2(H1.x, w2, a2); a3 = ffma2(H1.y, w2, a3);
                    }
                }
            } else {
                const float* base = is_in ? &xin[t & (XBUF - 1)][0] : h_t;
                const ulonglong2* sp = (const ulonglong2*)(base + kbase * BT);
                #pragma unroll
                for (int k = 0; k < KITER; k++) {
                    ulonglong2 S0 = sp[2 * k], S1 = sp[2 * k + 1];
                    ull w2 = splat2(w_r[k]);
                    a0 = ffma2(S0.x, w2, a0); a1 = ffma2(S0.y, w2, a1);
                    a2 = ffma2(S1.x, w2, a2); a3 = ffma2(S1.y, w2, a3);
                }
            }
            if (active) {
                ulonglong2* gp = (ulonglong2*)gbuf[quad];
                ulonglong2 s0; s0.x = a0; s0.y = a1;
                ulonglong2 s1; s1.x = a2; s1.y = a3;
                gp[j * 2 + 0] = s0;
                gp[j * 2 + 1] = s1;
            }
        } else {
            // comm warp: prefetch xin(t+DPRE), backpressure, (L3) output proj
            if (role > 0 && t + DPRE < TN) {
                if (tid == COMM0) wait_ge(&g_prod[role - 1][g], (unsigned)(t + DPRE + 1));
                __syncwarp();
                const float4* src = (const float4*)(ring_in + ((t + DPRE) & (NSLOT - 1)) * HN * BT);
                float4* dst = (float4*)xin[(t + DPRE) & (XBUF - 1)];
                for (int i = tid - COMM0; i < HN * BT / 4; i += 32) dst[i] = ldcg4(src + i);
                __syncwarp();
                if (tid == COMM0) st_rel(&g_cons[role - 1][g], (unsigned)(t + DPRE + 1));
            }
            if (role < 2 && t >= NSLOT && tid == COMM0)
                wait_ge(&g_cons[role][g], (unsigned)(t - (NSLOT - 1)));
            if (role == 2 && t > 0) {
                int b = tid - COMM0;
                if (b < BT) {
                    float a = blv;
                    #pragma unroll
                    for (int u = 0; u < HN; u++) a += h_t[u * BT + b] * wl_s[u];
                    out[(size_t)(g * BT + b) * TN + (t - 1)] = a;
                }
            }
        }
        __syncthreads();   // gates ready; h_t free; xin(t+DPRE) landed

        // ================= P1: cell update (sum the four quarters) ============
        if (tid < HN * BT) {
            const int i = tid;
            float gi = gbuf[0][i]           + gbuf[1][i]
                     + gbuf[2][i]           + gbuf[3][i];
            float gf = gbuf[0][HN*BT + i]   + gbuf[1][HN*BT + i]
                     + gbuf[2][HN*BT + i]   + gbuf[3][HN*BT + i];
            float gg = gbuf[0][2*HN*BT + i] + gbuf[1][2*HN*BT + i]
                     + gbuf[2][2*HN*BT + i] + gbuf[3][2*HN*BT + i];
            float go = gbuf[0][3*HN*BT + i] + gbuf[1][3*HN*BT + i]
                     + gbuf[2][3*HN*BT + i] + gbuf[3][3*HN*BT + i];
            float c  = sigf(gf) * c_s[i] + sigf(gi) * tanhfast(gg);
            float h  = sigf(go) * tanhfast(c);
            c_s[i] = c;
            h_t[i] = h;
            if (role < 2) ring_out[(t & (NSLOT - 1)) * HN * BT + i] = h;
        }
        __syncthreads();   // h_t / ring slot complete
        if (role < 2 && tid == 0) st_rel(&g_prod[role][g], (unsigned)(t + 1));
    }

    // epilogue: out for t = TN-1 (from final h_t of layer 3)
    if (role == 2 && tid < BT) {
        float a = blv;
        #pragma unroll
        for (int u = 0; u < HN; u++) a += h_t[u * BT + tid] * wl_s[u];
        out[(size_t)(g * BT + tid) * TN + (TN - 1)] = a;
    }
}

extern "C" void kernel_launch(void* const* d_in, const int* in_sizes, int n_in,
                              void* d_out, int out_size)
{
    (void)in_sizes; (void)n_in; (void)out_size;
    const float* x    = (const float*)d_in[0];
    const float* Wih1 = (const float*)d_in[1];
    const float* Whh1 = (const float*)d_in[2];
    const float* bih1 = (const float*)d_in[3];
    const float* bhh1 = (const float*)d_in[4];
    const float* Wih  = (const float*)d_in[5];
    const float* Whh  = (const float*)d_in[6];
    const float* bih  = (const float*)d_in[7];
    const float* bhh  = (const float*)d_in[8];
    const float* Wl   = (const float*)d_in[9];
    const float* bl   = (const float*)d_in[10];
    float* out = (float*)d_out;

    reset_kernel<<<1, 64>>>();
    lstm_kernel<<<3 * NG, NTH>>>(x, Wih1, Whh1, bih1, bhh1,
                                 Wih, Whh, bih, bhh, Wl, bl, out);
}

// round 8
// speedup vs baseline: 1.0443x; 1.0443x over previous
#include <cuda_runtime.h>

// ---------------------------------------------------------------------------
// 5-layer stacked LSTM, H=51, B=256, T=2048. Output depends only on layer-3 h
// => layers 4,5 dead. 3 roles (L1,L2,L3) x 32 batch groups = 96 CTAs.
// CROSSBAR-OPTIMIZED GEMV: each thread owns the 4 gate rows (i,f,g,o) of one
// hidden unit over half of k -> one 32B broadcast h-load feeds 16 FFMA2
// (4x fewer LDS wavefronts than 1-row/thread). 204 compute lanes in 7 warps
// (quadrant = lane-level, branch-uniform) + 1 comm warp (deep prefetch D=4).
// ---------------------------------------------------------------------------

#define HN 51
#define NJ 204
#define TN 2048
#define NG 32
#define BT 8
#define NSLOT 16             // ring slots (power of 2)
#define XBUF 8               // xin SMEM slots (power of 2), > DPRE
#define DPRE 4               // prefetch distance
#define NTH 256
#define COMM0 224            // first tid of comm warp (warp 7)
#define KIT 26               // k iterations per half

typedef unsigned long long ull;

__device__ float    g_hbuf[2][NG][NSLOT][HN * BT];
__device__ unsigned g_prod[2][NG];
__device__ unsigned g_cons[2][NG];

__device__ __forceinline__ unsigned ld_acq(const unsigned* p) {
    unsigned v;
    asm volatile("ld.global.acquire.gpu.u32 %0, [%1];" : "=r"(v) : "l"(p));
    return v;
}
__device__ __forceinline__ void st_rel(unsigned* p, unsigned v) {
    asm volatile("st.global.release.gpu.u32 [%0], %1;" :: "l"(p), "r"(v));
}
__device__ __forceinline__ void wait_ge(unsigned* p, unsigned v) {
    if (ld_acq(p) >= v) return;
    while (ld_acq(p) < v) __nanosleep(32);
}
__device__ __forceinline__ float4 ldcg4(const float4* p) {
    float4 v;
    asm volatile("ld.global.cg.v4.f32 {%0,%1,%2,%3}, [%4];"
                 : "=f"(v.x), "=f"(v.y), "=f"(v.z), "=f"(v.w) : "l"(p));
    return v;
}
__device__ __forceinline__ ull ffma2(ull a, ull b, ull c) {
    ull d;
    asm("fma.rn.f32x2 %0, %1, %2, %3;" : "=l"(d) : "l"(a), "l"(b), "l"(c));
    return d;
}
__device__ __forceinline__ ull splat2(float x) {
    ull d; unsigned u = __float_as_uint(x);
    asm("mov.b64 %0, {%1, %2};" : "=l"(d) : "r"(u), "r"(u));
    return d;
}
__device__ __forceinline__ float sigf(float x) {
    return __fdividef(1.f, 1.f + __expf(-x));
}
__device__ __forceinline__ float tanhfast(float x) {
    return 2.f * __fdividef(1.f, 1.f + __expf(-2.f * x)) - 1.f;
}

__global__ void __launch_bounds__(64, 1) reset_kernel() {
    int i = threadIdx.x;
    if (i < NG) {
        g_prod[0][i] = 0; g_prod[1][i] = 0;
        g_cons[0][i] = 0; g_cons[1][i] = 0;
    }
}

__global__ void __launch_bounds__(NTH, 1) lstm_kernel(
    const float* __restrict__ x,    const float* __restrict__ Wih1,
    const float* __restrict__ Whh1, const float* __restrict__ bih1,
    const float* __restrict__ bhh1, const float* __restrict__ Wih,
    const float* __restrict__ Whh,  const float* __restrict__ bih,
    const float* __restrict__ bhh,  const float* __restrict__ Wl,
    const float* __restrict__ bl,   float* __restrict__ out)
{
    __shared__ __align__(16) float xin[XBUF][HN * BT];  // layer-input slots
    __shared__ __align__(16) float h_t[HN * BT];        // [k][b]
    __shared__ __align__(16) float c_s[HN * BT];
    __shared__ __align__(16) float gbuf[4][NJ * BT];    // partial gates / quadrant
    __shared__ __align__(16) float xchunk[32 * BT];     // [q][b], L1 raw-x prefetch
    __shared__ float wl_s[52];

    const int tid  = threadIdx.x;
    const int role = blockIdx.x / NG;   // 0=L1, 1=L2, 2=L3
    const int g    = blockIdx.x % NG;

    const bool is_comm = (tid >= COMM0);
    const int  cid     = is_comm ? 0 : tid;
    const bool active  = (!is_comm) && (cid < NJ);
    const int  part    = cid / 102;            // 0: input GEMV, 1: recurrent GEMV
    const int  kh      = (cid % 102) / 51;     // k half
    const int  j       = cid % 51;             // hidden unit (gate rows j,51+j,...)
    const int  quad    = part * 2 + kh;
    const int  kbase   = kh * 25;

    // ---------------- per-thread register weights ----------------
    float w_r[4][KIT];
    ull bias2[4], w1_2[4];
    #pragma unroll
    for (int G = 0; G < 4; G++) { bias2[G] = 0; w1_2[G] = 0; }
    #pragma unroll
    for (int G = 0; G < 4; G++)
        #pragma unroll
        for (int k = 0; k < KIT; k++) w_r[G][k] = 0.f;

    if (active) {
        if (part == 1) {
            const float* W = (role == 0) ? Whh1 : (Whh + (role - 1) * NJ * HN);
            #pragma unroll
            for (int G = 0; G < 4; G++)
                #pragma unroll
                for (int k = 0; k < KIT; k++)
                    w_r[G][k] = (k == 0 && kh) ? 0.f : W[(G * 51 + j) * HN + kbase + k];
        } else if (role > 0) {
            const int l = role - 1;
            const float* W = Wih + l * NJ * HN;
            #pragma unroll
            for (int G = 0; G < 4; G++)
                #pragma unroll
                for (int k = 0; k < KIT; k++)
                    w_r[G][k] = (k == 0 && kh) ? 0.f : W[(G * 51 + j) * HN + kbase + k];
            if (kh == 0)
                #pragma unroll
                for (int G = 0; G < 4; G++)
                    bias2[G] = splat2(bih[l * NJ + G * 51 + j] + bhh[l * NJ + G * 51 + j]);
        } else {  // role 0, input part: rank-1 x term (kh==0 lanes only)
            if (kh == 0) {
                #pragma unroll
                for (int G = 0; G < 4; G++) {
                    w1_2[G]  = splat2(Wih1[G * 51 + j]);
                    bias2[G] = splat2(bih1[G * 51 + j] + bhh1[G * 51 + j]);
                }
            }
        }
    }
    if (role == 2 && tid < HN) wl_s[tid] = Wl[tid];
    const float blv = (role == 2) ? bl[0] : 0.f;
    for (int i = tid; i < HN * BT; i += NTH) { h_t[i] = 0.f; c_s[i] = 0.f; }
    for (int i = tid; i < 4 * NJ * BT; i += NTH) (&gbuf[0][0])[i] = 0.f;
    __syncthreads();

    float*       ring_out = (role < 2) ? &g_hbuf[role][g][0][0]     : (float*)0;
    const float* ring_in  = (role > 0) ? &g_hbuf[role - 1][g][0][0] : (const float*)0;

    // ---- prologue: comm warp prefetches slots 0..DPRE-1 (persistent lead) ----
    if (role > 0 && is_comm) {
        for (int d = 0; d < DPRE; d++) {
            if (tid == COMM0) wait_ge(&g_prod[role - 1][g], (unsigned)(d + 1));
            __syncwarp();
            const float4* src = (const float4*)(ring_in + (d & (NSLOT - 1)) * HN * BT);
            float4* dst = (float4*)xin[d & (XBUF - 1)];
            for (int i = tid - COMM0; i < HN * BT / 4; i += 32) dst[i] = ldcg4(src + i);
            __syncwarp();
            if (tid == COMM0) st_rel(&g_cons[role - 1][g], (unsigned)(d + 1));
        }
    }
    __syncthreads();

    for (int t = 0; t < TN; t++) {
        // ---- L1: refill 32-step x chunk (coalesced), transposed [q][b] ----
        if (role == 0 && (t & 31) == 0) {
            int b = tid >> 5, q = tid & 31;
            xchunk[q * BT + b] = x[(size_t)(g * BT + b) * TN + t + q];
            __syncthreads();
        }

        // ================= P0: 4-row x half-k GEMV tiles + comm =================
        if (!is_comm) {
            if (role == 0 && part == 0) {
                // rank-1 input term, kh==0 lanes only
                if (active && kh == 0) {
                    const ulonglong2* xp = (const ulonglong2*)&xchunk[(t & 31) * BT];
                    ulonglong2 X0 = xp[0], X1 = xp[1];
                    #pragma unroll
                    for (int G = 0; G < 4; G++) {
                        ull a0 = ffma2(X0.x, w1_2[G], bias2[G]);
                        ull a1 = ffma2(X0.y, w1_2[G], bias2[G]);
                        ull a2 = ffma2(X1.x, w1_2[G], bias2[G]);
                        ull a3 = ffma2(X1.y, w1_2[G], bias2[G]);
                        ulonglong2 s0; s0.x = a0; s0.y = a1;
                        ulonglong2 s1; s1.x = a2; s1.y = a3;
                        *(ulonglong2*)&gbuf[0][(G * 51 + j) * BT]     = s0;
                        *(ulonglong2*)&gbuf[0][(G * 51 + j) * BT + 4] = s1;
                    }
                }
            } else {
                const float* base = (part == 0) ? &xin[t & (XBUF - 1)][0] : h_t;
                const ulonglong2* sp = (const ulonglong2*)(base + kbase * BT);
                ull acc[4][4];
                #pragma unroll
                for (int G = 0; G < 4; G++) {
                    acc[G][0] = bias2[G]; acc[G][1] = bias2[G];
                    acc[G][2] = bias2[G]; acc[G][3] = bias2[G];
                }
                #pragma unroll
                for (int k = 0; k < KIT; k++) {
                    ulonglong2 S0 = sp[2 * k], S1 = sp[2 * k + 1];
                    #pragma unroll
                    for (int G = 0; G < 4; G++) {
                        ull w2 = splat2(w_r[G][k]);
                        acc[G][0] = ffma2(S0.x, w2, acc[G][0]);
                        acc[G][1] = ffma2(S0.y, w2, acc[G][1]);
                        acc[G][2] = ffma2(S1.x, w2, acc[G][2]);
                        acc[G][3] = ffma2(S1.y, w2, acc[G][3]);
                    }
                }
                if (active) {
                    #pragma unroll
                    for (int G = 0; G < 4; G++) {
                        ulonglong2 s0; s0.x = acc[G][0]; s0.y = acc[G][1];
                        ulonglong2 s1; s1.x = acc[G][2]; s1.y = acc[G][3];
                        *(ulonglong2*)&gbuf[quad][(G * 51 + j) * BT]     = s0;
                        *(ulonglong2*)&gbuf[quad][(G * 51 + j) * BT + 4] = s1;
                    }
                }
            }
        } else {
            // comm warp: prefetch xin(t+DPRE), backpressure, (L3) output proj
            if (role > 0 && t + DPRE < TN) {
                if (tid == COMM0) wait_ge(&g_prod[role - 1][g], (unsigned)(t + DPRE + 1));
                __syncwarp();
                const float4* src = (const float4*)(ring_in + ((t + DPRE) & (NSLOT - 1)) * HN * BT);
                float4* dst = (float4*)xin[(t + DPRE) & (XBUF - 1)];
                for (int i = tid - COMM0; i < HN * BT / 4; i += 32) dst[i] = ldcg4(src + i);
                __syncwarp();
                if (tid == COMM0) st_rel(&g_cons[role - 1][g], (unsigned)(t + DPRE + 1));
            }
            if (role < 2 && t >= NSLOT && tid == COMM0)
                wait_ge(&g_cons[role][g], (unsigned)(t - (NSLOT - 1)));
            if (role == 2 && t > 0) {
                int b = tid - COMM0;
                if (b < BT) {
                    float a = blv;
                    #pragma unroll
                    for (int u = 0; u < HN; u++) a += h_t[u * BT + b] * wl_s[u];
                    out[(size_t)(g * BT + b) * TN + (t - 1)] = a;
                }
            }
        }
        __syncthreads();   // gates ready; h_t free; xin(t+DPRE) landed

        // ================= P1: cell update (sum the four quadrants) ============
        for (int i = tid; i < HN * BT; i += NTH) {
            float gi = gbuf[0][i]           + gbuf[1][i]
                     + gbuf[2][i]           + gbuf[3][i];
            float gf = gbuf[0][HN*BT + i]   + gbuf[1][HN*BT + i]
                     + gbuf[2][HN*BT + i]   + gbuf[3][HN*BT + i];
            float gg = gbuf[0][2*HN*BT + i] + gbuf[1][2*HN*BT + i]
                     + gbuf[2][2*HN*BT + i] + gbuf[3][2*HN*BT + i];
            float go = gbuf[0][3*HN*BT + i] + gbuf[1][3*HN*BT + i]
                     + gbuf[2][3*HN*BT + i] + gbuf[3][3*HN*BT + i];
            float c  = sigf(gf) * c_s[i] + sigf(gi) * tanhfast(gg);
            float h  = sigf(go) * tanhfast(c);
            c_s[i] = c;
            h_t[i] = h;
            if (role < 2) ring_out[(t & (NSLOT - 1)) * HN * BT + i] = h;
        }
        __syncthreads();   // h_t / ring slot complete
        if (role < 2 && tid == 0) st_rel(&g_prod[role][g], (unsigned)(t + 1));
    }

    // epilogue: out for t = TN-1 (from final h_t of layer 3)
    if (role == 2 && tid < BT) {
        float a = blv;
        #pragma unroll
        for (int u = 0; u < HN; u++) a += h_t[u * BT + tid] * wl_s[u];
        out[(size_t)(g * BT + tid) * TN + (TN - 1)] = a;
    }
}

extern "C" void kernel_launch(void* const* d_in, const int* in_sizes, int n_in,
                              void* d_out, int out_size)
{
    (void)in_sizes; (void)n_in; (void)out_size;
    const float* x    = (const float*)d_in[0];
    const float* Wih1 = (const float*)d_in[1];
    const float* Whh1 = (const float*)d_in[2];
    const float* bih1 = (const float*)d_in[3];
    const float* bhh1 = (const float*)d_in[4];
    const float* Wih  = (const float*)d_in[5];
    const float* Whh  = (const float*)d_in[6];
    const float* bih  = (const float*)d_in[7];
    const float* bhh  = (const float*)d_in[8];
    const float* Wl   = (const float*)d_in[9];
    const float* bl   = (const float*)d_in[10];
    float* out = (float*)d_out;

    reset_kernel<<<1, 64>>>();
    lstm_kernel<<<3 * NG, NTH>>>(x, Wih1, Whh1, bih1, bhh1,
                                 Wih, Whh, bih, bhh, Wl, bl, out);
}